// round 16
// baseline (speedup 1.0000x reference)
#include <cuda_runtime.h>
#include <mma.h>
#include <cstdint>

using namespace nvcuda;

#define Bp 32
#define Np 1024
#define Mp 1024
#define Dp 128

// Scratch (device globals; allocation is forbidden everywhere)
__device__ float g_Xc[Bp * Np * Dp];            // X * tanh(W@A^T+b)  [b][n][d] (fp32)
__device__ float g_Xr[Bp * Np * Dp];            // tf32-rounded Xs
__device__ float g_Yr[Bp * Mp * Dp];            // tf32-rounded Ys
__device__ float g_P[(size_t)Bp * Np * Mp];     // P = tf32r(1+e^z)   [b][n][m]
__device__ float g_rs[Bp * Np];                 // row sums of rounded P
__device__ float g_cs[Bp * Mp];                 // col sums of rounded P

// ---------------------------------------------------------------------------
__device__ __forceinline__ uint32_t s2u(const void* p) {
    uint32_t a;
    asm("{ .reg .u64 t; cvta.to.shared.u64 t, %1; cvt.u32.u64 %0, t; }"
        : "=r"(a) : "l"(p));
    return a;
}
__device__ __forceinline__ void cpa16(uint32_t d, const void* s) {
    asm volatile("cp.async.cg.shared.global [%0], [%1], 16;"
                 :: "r"(d), "l"(s) : "memory");
}
#define CP_COMMIT() asm volatile("cp.async.commit_group;" ::: "memory")
#define CP_WAIT1()  asm volatile("cp.async.wait_group 1;" ::: "memory")
#define CP_WAIT0()  asm volatile("cp.async.wait_group 0;" ::: "memory")

__device__ __forceinline__ float tf32r(float x) {
    return wmma::__float_to_tf32(x);
}
__device__ __forceinline__ unsigned long long fma2(unsigned long long a,
                                                   unsigned long long b,
                                                   unsigned long long c) {
    unsigned long long d;
    asm("fma.rn.f32x2 %0, %1, %2, %3;" : "=l"(d) : "l"(a), "l"(b), "l"(c));
    return d;
}
__device__ __forceinline__ float2 up2(unsigned long long u) {
    float2 f;
    asm("mov.b64 {%0, %1}, %2;" : "=f"(f.x), "=f"(f.y) : "l"(u));
    return f;
}

typedef wmma::fragment<wmma::matrix_a, 16, 16, 8, wmma::precision::tf32,
                       wmma::row_major> FragAR;
typedef wmma::fragment<wmma::matrix_a, 16, 16, 8, wmma::precision::tf32,
                       wmma::col_major> FragAC;
typedef wmma::fragment<wmma::matrix_b, 16, 16, 8, wmma::precision::tf32,
                       wmma::row_major> FragBR;
typedef wmma::fragment<wmma::accumulator, 16, 16, 8, float> FragC;

// attn smem: 3-stage ring. Stage = A(128x20 = 2560 fl) + B(16x68 = 1088 fl)
#define STAGE_FL 3648
#define AB_OFF   2560
#define SMEM_ATTN (3 * STAGE_FL * 4)   // 43776 B -> 4 CTAs/SM

// ---------------------------------------------------------------------------
// k_prep: tf32-rounded copies of Xs/Ys + zero the softmax accumulators.
// 4096 blocks of 256 handle the copies; blocks 0..127 also zero rs/cs.
// ---------------------------------------------------------------------------
__global__ void k_prep(const float* __restrict__ Xs, const float* __restrict__ Ys) {
    size_t i = ((size_t)blockIdx.x * 256 + threadIdx.x) * 4;
    float4 x = *(const float4*)(Xs + i);
    float4 y = *(const float4*)(Ys + i);
    *(float4*)(g_Xr + i) =
        make_float4(tf32r(x.x), tf32r(x.y), tf32r(x.z), tf32r(x.w));
    *(float4*)(g_Yr + i) =
        make_float4(tf32r(y.x), tf32r(y.y), tf32r(y.z), tf32r(y.w));
    if (blockIdx.x < 128) {
        int j = blockIdx.x * 256 + threadIdx.x;
        g_rs[j] = 0.f;
        g_cs[j] = 0.f;
    }
}

// ---------------------------------------------------------------------------
// K1: Xc[r][e] = Xs[r][e] * tanh( sum_d W[r][d]*Aw[e][d] + Ab[e] )  (verified)
// ---------------------------------------------------------------------------
__global__ __launch_bounds__(256) void k_coeff(const float* __restrict__ W,
                                               const float* __restrict__ Aw,
                                               const float* __restrict__ Ab,
                                               const float* __restrict__ Xs) {
    const int tx = threadIdx.x, ty = threadIdx.y;
    const int tid = ty * 16 + tx;
    const int r0 = blockIdx.x * 64;

    __shared__ __align__(16) float Ws[64][32];
    __shared__ __align__(16) float Awt[32][132];

    float acc[4][8];
#pragma unroll
    for (int i = 0; i < 4; i++)
#pragma unroll
        for (int j = 0; j < 8; j++) acc[i][j] = 0.f;

    for (int k0 = 0; k0 < Dp; k0 += 32) {
#pragma unroll
        for (int it = 0; it < 2; it++) {
            int id = tid + it * 256;
            int r = id >> 3, q = id & 7;
            *(float4*)&Ws[r][q * 4] =
                *(const float4*)(W + (size_t)(r0 + r) * Dp + k0 + q * 4);
        }
#pragma unroll
        for (int it = 0; it < 4; it++) {
            int id = tid + it * 256;
            int e = id >> 3, q = id & 7;
            float4 v = *(const float4*)(Aw + (size_t)e * Dp + k0 + q * 4);
            Awt[q * 4 + 0][e] = v.x;
            Awt[q * 4 + 1][e] = v.y;
            Awt[q * 4 + 2][e] = v.z;
            Awt[q * 4 + 3][e] = v.w;
        }
        __syncthreads();
#pragma unroll
        for (int k = 0; k < 32; k++) {
            float w0 = Ws[ty * 4 + 0][k];
            float w1 = Ws[ty * 4 + 1][k];
            float w2 = Ws[ty * 4 + 2][k];
            float w3 = Ws[ty * 4 + 3][k];
            float4 a0 = *(const float4*)&Awt[k][tx * 8];
            float4 a1 = *(const float4*)&Awt[k][tx * 8 + 4];
            float av[8] = {a0.x, a0.y, a0.z, a0.w, a1.x, a1.y, a1.z, a1.w};
#pragma unroll
            for (int j = 0; j < 8; j++) {
                acc[0][j] = fmaf(w0, av[j], acc[0][j]);
                acc[1][j] = fmaf(w1, av[j], acc[1][j]);
                acc[2][j] = fmaf(w2, av[j], acc[2][j]);
                acc[3][j] = fmaf(w3, av[j], acc[3][j]);
            }
        }
        __syncthreads();
    }

    float abv[8];
    *(float4*)&abv[0] = *(const float4*)(Ab + tx * 8);
    *(float4*)&abv[4] = *(const float4*)(Ab + tx * 8 + 4);

#pragma unroll
    for (int i = 0; i < 4; i++) {
        int r = r0 + ty * 4 + i;
        const float* xr = Xs + (size_t)r * Dp + tx * 8;
        float4 x0 = *(const float4*)xr;
        float4 x1 = *(const float4*)(xr + 4);
        float c[8];
#pragma unroll
        for (int j = 0; j < 8; j++) c[j] = tanhf(acc[i][j] + abv[j]);
        float4 o0 = make_float4(x0.x * c[0], x0.y * c[1], x0.z * c[2], x0.w * c[3]);
        float4 o1 = make_float4(x1.x * c[4], x1.y * c[5], x1.z * c[6], x1.w * c[7]);
        float* dst = g_Xc + (size_t)r * Dp + tx * 8;
        *(float4*)dst = o0;
        *(float4*)(dst + 4) = o1;
    }
}

// ---------------------------------------------------------------------------
// K2 v4 (FFMA2 k-quad vectorized):
//  128 threads / CTA, tile 64n x 64m, micro 8n x 4m, 4 CTAs/SM.
//  Both tiles stored as natural float4 k-quads: T[kq2][row] = row's k-quad.
//  One LDS.128 serves TWO k-pairs -> 12 LDS instrs per 64 FMA2 per warp.
//  K=128 in chunks of 16 (8 barriers), double-buffered.
//  s out (exact fp32); P = tf32r(1+e^z) out; row/col sums of ROUNDED P.
// ---------------------------------------------------------------------------
__global__ __launch_bounds__(128, 4) void k_scores(const float* __restrict__ Ys,
                                                   float* __restrict__ out_s) {
    const int tid = threadIdx.x;
    const int tx = tid & 15, ty = tid >> 4;     // tx: m group, ty: n group (0..7)
    const int mt = blockIdx.x, nt = blockIdx.y, b = blockIdx.z;

    __shared__ __align__(16) float4 As4[2][4][66];  // [kq2][n-row] = k-quad
    __shared__ __align__(16) float4 Bt4[2][4][66];  // [kq2][m-row] = k-quad
    __shared__ float scs[64];

    unsigned long long acc[8][4];
#pragma unroll
    for (int i = 0; i < 8; i++)
#pragma unroll
        for (int j = 0; j < 4; j++) acc[i][j] = 0ULL;

    const float* Xc = g_Xc + (size_t)(b * Np + nt * 64) * Dp;
    const float* Yb = Ys + (size_t)(b * Mp + mt * 64) * Dp;

    const int nl = tid >> 1, kq = tid & 1;   // loader: 64 rows x 2 k-octets
    if (tid < 64) scs[tid] = 0.f;

    // prologue: chunk 0 (16 k). Each thread: 2 float4 per tile.
    {
        const float* ax = Xc + (size_t)nl * Dp + kq * 8;
        const float* by = Yb + (size_t)nl * Dp + kq * 8;
        As4[0][2 * kq + 0][nl] = *(const float4*)ax;
        As4[0][2 * kq + 1][nl] = *(const float4*)(ax + 4);
        Bt4[0][2 * kq + 0][nl] = *(const float4*)by;
        Bt4[0][2 * kq + 1][nl] = *(const float4*)(by + 4);
    }
    __syncthreads();

    const int NC = Dp / 16;  // 8
#pragma unroll 2
    for (int c = 0; c < NC; c++) {
        const int cur = c & 1;
        float4 pa0, pa1, pb0, pb1;
        const bool has = (c + 1 < NC);
        if (has) {
            const float* ax = Xc + (size_t)nl * Dp + (c + 1) * 16 + kq * 8;
            const float* by = Yb + (size_t)nl * Dp + (c + 1) * 16 + kq * 8;
            pa0 = *(const float4*)ax;
            pa1 = *(const float4*)(ax + 4);
            pb0 = *(const float4*)by;
            pb1 = *(const float4*)(by + 4);
        }
#pragma unroll
        for (int kq2 = 0; kq2 < 4; kq2++) {
            // A: 8 n-rows, each a k-quad = 2 k-pairs
            ulonglong2 aq[8];
#pragma unroll
            for (int i = 0; i < 8; i++)
                aq[i] = *(const ulonglong2*)&As4[cur][kq2][ty * 8 + i];
            // B: 4 m-groups
            ulonglong2 bq[4];
#pragma unroll
            for (int j = 0; j < 4; j++)
                bq[j] = *(const ulonglong2*)&Bt4[cur][kq2][j * 16 + tx];
            // k-pair 0 (x), then k-pair 1 (y)
#pragma unroll
            for (int i = 0; i < 8; i++)
#pragma unroll
                for (int j = 0; j < 4; j++)
                    acc[i][j] = fma2(aq[i].x, bq[j].x, acc[i][j]);
#pragma unroll
            for (int i = 0; i < 8; i++)
#pragma unroll
                for (int j = 0; j < 4; j++)
                    acc[i][j] = fma2(aq[i].y, bq[j].y, acc[i][j]);
        }
        if (has) {
            const int nx = cur ^ 1;
            As4[nx][2 * kq + 0][nl] = pa0;
            As4[nx][2 * kq + 1][nl] = pa1;
            Bt4[nx][2 * kq + 0][nl] = pb0;
            Bt4[nx][2 * kq + 1][nl] = pb1;
        }
        __syncthreads();
    }

    // epilogue: z = pair-sum; s (exact fp32), rounded P, sums of rounded P.
    // n = nt*64 + ty*8 + i;  m = mt*64 + j*16 + tx.
    float csum[4];
#pragma unroll
    for (int j = 0; j < 4; j++) csum[j] = 0.f;

#pragma unroll
    for (int i = 0; i < 8; i++) {
        const size_t off =
            ((size_t)(b * Np + nt * 64 + ty * 8 + i)) * Mp + mt * 64;
        float rs = 0.f;
#pragma unroll
        for (int j = 0; j < 4; j++) {
            float2 zz = up2(acc[i][j]);
            float z = zz.x + zz.y;
            float p = 1.f + __expf(z);
            float pr = tf32r(p);
            out_s[off + j * 16 + tx] = __logf(p) - 0.5f;
            g_P[off + j * 16 + tx] = pr;
            rs += pr;
            csum[j] += pr;
        }
        rs += __shfl_xor_sync(0xFFFFFFFFu, rs, 1);
        rs += __shfl_xor_sync(0xFFFFFFFFu, rs, 2);
        rs += __shfl_xor_sync(0xFFFFFFFFu, rs, 4);
        rs += __shfl_xor_sync(0xFFFFFFFFu, rs, 8);
        if (tx == 0) atomicAdd(&g_rs[b * Np + nt * 64 + ty * 8 + i], rs);
    }

#pragma unroll
    for (int j = 0; j < 4; j++) atomicAdd(&scs[j * 16 + tx], csum[j]);
    __syncthreads();
    if (tid < 64) atomicAdd(&g_cs[b * Mp + mt * 64 + tid], scs[tid]);
}

// ---------------------------------------------------------------------------
// K3 (wmma tf32, latency-restructured — R12 WIN, unchanged):
//  128 threads / CTA (4 warps), CTA tile 128 rows x 64 cols (d half),
//  4 CTAs/SM, 3-stage ring, k-chunk 16.
// ---------------------------------------------------------------------------
__global__ __launch_bounds__(128, 4) void k_attn(float* __restrict__ out_x,
                                                 float* __restrict__ out_y) {
    extern __shared__ __align__(16) float smf[];
    const uint32_t sb = s2u(smf);
    const int t = threadIdx.x;
    const int w = t >> 5;
    const int rt = blockIdx.x;          // 128-row tile
    const int d0 = blockIdx.y * 64;     // d half
    const int b = blockIdx.z & 31;
    const int mode = blockIdx.z >> 5;

    const float* Pb = g_P + (size_t)b * Np * Mp;
    const float* Bsrc = mode ? (g_Xr + (size_t)b * Np * Dp)
                             : (g_Yr + (size_t)b * Mp * Dp);

    const int m0 = w * 32;              // warp row base (warp tile 32x64)

    FragC acc[2][4];
#pragma unroll
    for (int i = 0; i < 2; i++)
#pragma unroll
        for (int j = 0; j < 4; j++) wmma::fill_fragment(acc[i][j], 0.f);

    // stage layout: A @ +0 (mode0: [128][20]; mode1: [16][132]); B @ +2560 ([16][68])
    auto load_chunk = [&](int c, int f) {
        uint32_t Ad = sb + (uint32_t)(f * STAGE_FL) * 4;
        uint32_t Bd = Ad + AB_OFF * 4;
        if (mode == 0) {
#pragma unroll
            for (int o = 0; o < 4; o++) {
                int idx = t + o * 128;
                int row = idx >> 2, q = idx & 3;
                cpa16(Ad + (uint32_t)((row * 20 + q * 4) * 4),
                      Pb + (size_t)(rt * 128 + row) * Mp + c * 16 + q * 4);
            }
        } else {
#pragma unroll
            for (int o = 0; o < 4; o++) {
                int idx = t + o * 128;
                int kr = idx >> 5, mq = idx & 31;
                cpa16(Ad + (uint32_t)((kr * 132 + mq * 4) * 4),
                      Pb + (size_t)(c * 16 + kr) * Mp + rt * 128 + mq * 4);
            }
        }
#pragma unroll
        for (int o = 0; o < 2; o++) {
            int idx = t + o * 128;
            int kr = idx >> 4, dq = idx & 15;
            cpa16(Bd + (uint32_t)((kr * 68 + dq * 4) * 4),
                  Bsrc + (size_t)(c * 16 + kr) * Dp + d0 + dq * 4);
        }
        CP_COMMIT();
    };

    load_chunk(0, 0);
    load_chunk(1, 1);
    const int NC = 64;   // K = 1024 in chunks of 16
    for (int c = 0; c < NC; c++) {
        if (c + 1 < NC) CP_WAIT1(); else CP_WAIT0();
        __syncthreads();
        if (c + 2 < NC) load_chunk(c + 2, (c + 2) % 3);
        const float* As_ = smf + (c % 3) * STAGE_FL;
        const float* Bs_ = As_ + AB_OFF;
        if (mode == 0) {
#pragma unroll
            for (int s = 0; s < 2; s++) {
                FragAR af[2];
                FragBR bf[4];
#pragma unroll
                for (int i = 0; i < 2; i++)
                    wmma::load_matrix_sync(af[i], As_ + (m0 + i * 16) * 20 + s * 8, 20);
#pragma unroll
                for (int j = 0; j < 4; j++)
                    wmma::load_matrix_sync(bf[j], Bs_ + (s * 8) * 68 + j * 16, 68);
#pragma unroll
                for (int i = 0; i < 2; i++)
#pragma unroll
                    for (int j = 0; j < 4; j++)
                        wmma::mma_sync(acc[i][j], af[i], bf[j], acc[i][j]);
            }
        } else {
#pragma unroll
            for (int s = 0; s < 2; s++) {
                FragAC af[2];
                FragBR bf[4];
#pragma unroll
                for (int i = 0; i < 2; i++)
                    wmma::load_matrix_sync(af[i], As_ + (s * 8) * 132 + m0 + i * 16, 132);
#pragma unroll
                for (int j = 0; j < 4; j++)
                    wmma::load_matrix_sync(bf[j], Bs_ + (s * 8) * 68 + j * 16, 68);
#pragma unroll
                for (int i = 0; i < 2; i++)
#pragma unroll
                    for (int j = 0; j < 4; j++)
                        wmma::mma_sync(acc[i][j], af[i], bf[j], acc[i][j]);
            }
        }
    }
    __syncthreads();

    // stash to smem [128][68], then normalized coalesced write-out
#pragma unroll
    for (int i = 0; i < 2; i++)
#pragma unroll
        for (int j = 0; j < 4; j++)
            wmma::store_matrix_sync(smf + (m0 + i * 16) * 68 + j * 16,
                                    acc[i][j], 68, wmma::mem_row_major);
    __syncthreads();

    {
        const int r = t;   // each thread owns one output row (64 cols)
        const float inv =
            1.f / (mode ? g_cs[b * Mp + rt * 128 + r]
                        : g_rs[b * Np + rt * 128 + r]);
        const float* rowp = smf + r * 68;
        float* outp = (mode ? out_y : out_x) +
                      (size_t)(b * 1024 + rt * 128 + r) * Dp + d0;
#pragma unroll
        for (int j = 0; j < 16; j++) {
            float4 v = *(const float4*)(rowp + j * 4);
            *(float4*)(outp + j * 4) =
                make_float4(v.x * inv, v.y * inv, v.z * inv, v.w * inv);
        }
    }
}

// ---------------------------------------------------------------------------
extern "C" void kernel_launch(void* const* d_in, const int* in_sizes, int n_in,
                              void* d_out, int out_size) {
    const float* Xs = (const float*)d_in[0];
    const float* Ys = (const float*)d_in[1];
    const float* W  = (const float*)d_in[2];
    const float* Aw = (const float*)d_in[3];
    const float* Ab = (const float*)d_in[4];

    float* out = (float*)d_out;
    float* out_x = out;                               // [B,N,D]
    float* out_y = out_x + (size_t)Bp * Np * Dp;      // [B,M,D]
    float* out_s = out_y + (size_t)Bp * Mp * Dp;      // [B,N,M]

    cudaFuncSetAttribute(k_attn, cudaFuncAttributeMaxDynamicSharedMemorySize,
                         SMEM_ATTN);

    k_prep<<<4096, 256>>>(Xs, Ys);
    k_coeff<<<(Bp * Np) / 64, dim3(16, 16)>>>(W, Aw, Ab, Xs);
    k_scores<<<dim3(16, 16, 32), 128>>>(Ys, out_s);
    k_attn<<<dim3(8, 2, 64), 128, SMEM_ATTN>>>(out_x, out_y);
}

// round 17
// speedup vs baseline: 1.0066x; 1.0066x over previous
#include <cuda_runtime.h>
#include <mma.h>
#include <cstdint>

using namespace nvcuda;

#define Bp 32
#define Np 1024
#define Mp 1024
#define Dp 128

// Scratch (device globals; allocation is forbidden everywhere)
__device__ float g_Xc[Bp * Np * Dp];            // X * tanh(W@A^T+b)  [b][n][d] (fp32)
__device__ float g_Xr[Bp * Np * Dp];            // tf32-rounded Xs
__device__ float g_Yr[Bp * Mp * Dp];            // tf32-rounded Ys
__device__ float g_P[(size_t)Bp * Np * Mp];     // P = tf32r(1+e^z)   [b][n][m]
__device__ float g_rs[Bp * Np];                 // row sums of rounded P
__device__ float g_cs[Bp * Mp];                 // col sums of rounded P

// ---------------------------------------------------------------------------
__device__ __forceinline__ uint32_t s2u(const void* p) {
    uint32_t a;
    asm("{ .reg .u64 t; cvta.to.shared.u64 t, %1; cvt.u32.u64 %0, t; }"
        : "=r"(a) : "l"(p));
    return a;
}
__device__ __forceinline__ void cpa16(uint32_t d, const void* s) {
    asm volatile("cp.async.cg.shared.global [%0], [%1], 16;"
                 :: "r"(d), "l"(s) : "memory");
}
#define CP_COMMIT() asm volatile("cp.async.commit_group;" ::: "memory")
#define CP_WAIT1()  asm volatile("cp.async.wait_group 1;" ::: "memory")
#define CP_WAIT0()  asm volatile("cp.async.wait_group 0;" ::: "memory")

__device__ __forceinline__ float tf32r(float x) {
    return wmma::__float_to_tf32(x);
}
__device__ __forceinline__ unsigned long long fma2(unsigned long long a,
                                                   unsigned long long b,
                                                   unsigned long long c) {
    unsigned long long d;
    asm("fma.rn.f32x2 %0, %1, %2, %3;" : "=l"(d) : "l"(a), "l"(b), "l"(c));
    return d;
}
__device__ __forceinline__ float2 up2(unsigned long long u) {
    float2 f;
    asm("mov.b64 {%0, %1}, %2;" : "=f"(f.x), "=f"(f.y) : "l"(u));
    return f;
}

typedef wmma::fragment<wmma::matrix_a, 16, 16, 8, wmma::precision::tf32,
                       wmma::row_major> FragAR;
typedef wmma::fragment<wmma::matrix_a, 16, 16, 8, wmma::precision::tf32,
                       wmma::col_major> FragAC;
typedef wmma::fragment<wmma::matrix_b, 16, 16, 8, wmma::precision::tf32,
                       wmma::row_major> FragBR;
typedef wmma::fragment<wmma::accumulator, 16, 16, 8, float> FragC;

// attn smem: 3-stage ring. Stage = A(128x20 = 2560 fl) + B(16x68 = 1088 fl)
#define STAGE_FL 3648
#define AB_OFF   2560
#define SMEM_ATTN (3 * STAGE_FL * 4)   // 43776 B -> 4 CTAs/SM

// ---------------------------------------------------------------------------
__global__ void k_zero() {
    int i = blockIdx.x * 256 + threadIdx.x;
    g_rs[i] = 0.f;
    g_cs[i] = 0.f;
}

// tf32-rounded copies of Xs and Ys. 4,194,304 elems / (256*4) = 4096 blocks.
__global__ void k_prep(const float* __restrict__ Xs, const float* __restrict__ Ys) {
    size_t i = ((size_t)blockIdx.x * 256 + threadIdx.x) * 4;
    float4 x = *(const float4*)(Xs + i);
    float4 y = *(const float4*)(Ys + i);
    *(float4*)(g_Xr + i) =
        make_float4(tf32r(x.x), tf32r(x.y), tf32r(x.z), tf32r(x.w));
    *(float4*)(g_Yr + i) =
        make_float4(tf32r(y.x), tf32r(y.y), tf32r(y.z), tf32r(y.w));
}

// ---------------------------------------------------------------------------
// K1: Xc[r][e] = Xs[r][e] * tanh( sum_d W[r][d]*Aw[e][d] + Ab[e] )  (verified)
// ---------------------------------------------------------------------------
__global__ __launch_bounds__(256) void k_coeff(const float* __restrict__ W,
                                               const float* __restrict__ Aw,
                                               const float* __restrict__ Ab,
                                               const float* __restrict__ Xs) {
    const int tx = threadIdx.x, ty = threadIdx.y;
    const int tid = ty * 16 + tx;
    const int r0 = blockIdx.x * 64;

    __shared__ __align__(16) float Ws[64][32];
    __shared__ __align__(16) float Awt[32][132];

    float acc[4][8];
#pragma unroll
    for (int i = 0; i < 4; i++)
#pragma unroll
        for (int j = 0; j < 8; j++) acc[i][j] = 0.f;

    for (int k0 = 0; k0 < Dp; k0 += 32) {
#pragma unroll
        for (int it = 0; it < 2; it++) {
            int id = tid + it * 256;
            int r = id >> 3, q = id & 7;
            *(float4*)&Ws[r][q * 4] =
                *(const float4*)(W + (size_t)(r0 + r) * Dp + k0 + q * 4);
        }
#pragma unroll
        for (int it = 0; it < 4; it++) {
            int id = tid + it * 256;
            int e = id >> 3, q = id & 7;
            float4 v = *(const float4*)(Aw + (size_t)e * Dp + k0 + q * 4);
            Awt[q * 4 + 0][e] = v.x;
            Awt[q * 4 + 1][e] = v.y;
            Awt[q * 4 + 2][e] = v.z;
            Awt[q * 4 + 3][e] = v.w;
        }
        __syncthreads();
#pragma unroll
        for (int k = 0; k < 32; k++) {
            float w0 = Ws[ty * 4 + 0][k];
            float w1 = Ws[ty * 4 + 1][k];
            float w2 = Ws[ty * 4 + 2][k];
            float w3 = Ws[ty * 4 + 3][k];
            float4 a0 = *(const float4*)&Awt[k][tx * 8];
            float4 a1 = *(const float4*)&Awt[k][tx * 8 + 4];
            float av[8] = {a0.x, a0.y, a0.z, a0.w, a1.x, a1.y, a1.z, a1.w};
#pragma unroll
            for (int j = 0; j < 8; j++) {
                acc[0][j] = fmaf(w0, av[j], acc[0][j]);
                acc[1][j] = fmaf(w1, av[j], acc[1][j]);
                acc[2][j] = fmaf(w2, av[j], acc[2][j]);
                acc[3][j] = fmaf(w3, av[j], acc[3][j]);
            }
        }
        __syncthreads();
    }

    float abv[8];
    *(float4*)&abv[0] = *(const float4*)(Ab + tx * 8);
    *(float4*)&abv[4] = *(const float4*)(Ab + tx * 8 + 4);

#pragma unroll
    for (int i = 0; i < 4; i++) {
        int r = r0 + ty * 4 + i;
        const float* xr = Xs + (size_t)r * Dp + tx * 8;
        float4 x0 = *(const float4*)xr;
        float4 x1 = *(const float4*)(xr + 4);
        float c[8];
#pragma unroll
        for (int j = 0; j < 8; j++) c[j] = tanhf(acc[i][j] + abv[j]);
        float4 o0 = make_float4(x0.x * c[0], x0.y * c[1], x0.z * c[2], x0.w * c[3]);
        float4 o1 = make_float4(x1.x * c[4], x1.y * c[5], x1.z * c[6], x1.w * c[7]);
        float* dst = g_Xc + (size_t)r * Dp + tx * 8;
        *(float4*)dst = o0;
        *(float4*)(dst + 4) = o1;
    }
}

// ---------------------------------------------------------------------------
// K2 v3 (FFMA2 k-paired, latency-restructured — R14 WIN, measured 240us):
//  128 threads / CTA, tile 64n x 64m, micro 8n x 4m, 4 CTAs/SM.
//  BOTH operands pair-interleaved float2 [kp][row] -> vectorized LDS,
//  no duplication. K=128 in chunks of 8, double-buffered.
//  s out (exact fp32); P = tf32r(1+e^z) out; row/col sums of ROUNDED P.
// ---------------------------------------------------------------------------
__global__ __launch_bounds__(128, 4) void k_scores(const float* __restrict__ Ys,
                                                   float* __restrict__ out_s) {
    const int tid = threadIdx.x;
    const int tx = tid & 15, ty = tid >> 4;     // tx: m group, ty: n group (0..7)
    const int mt = blockIdx.x, nt = blockIdx.y, b = blockIdx.z;

    __shared__ __align__(16) float2 As2[2][4][66];  // [kp][n-row], pair (2kp,2kp+1)
    __shared__ __align__(16) float2 Bt[2][4][66];   // [kp][m-row]
    __shared__ float scs[64];

    unsigned long long acc[8][4];
#pragma unroll
    for (int i = 0; i < 8; i++)
#pragma unroll
        for (int j = 0; j < 4; j++) acc[i][j] = 0ULL;

    const float* Xc = g_Xc + (size_t)(b * Np + nt * 64) * Dp;
    const float* Yb = Ys + (size_t)(b * Mp + mt * 64) * Dp;

    const int nl = tid >> 1, kq = tid & 1;   // loader: 64 rows x 2 k-quads
    if (tid < 64) scs[tid] = 0.f;

    // prologue: chunk 0
    {
        float4 va = *(const float4*)(Xc + (size_t)nl * Dp + kq * 4);
        float4 vb = *(const float4*)(Yb + (size_t)nl * Dp + kq * 4);
        As2[0][2 * kq + 0][nl] = make_float2(va.x, va.y);
        As2[0][2 * kq + 1][nl] = make_float2(va.z, va.w);
        Bt[0][2 * kq + 0][nl] = make_float2(vb.x, vb.y);
        Bt[0][2 * kq + 1][nl] = make_float2(vb.z, vb.w);
    }
    __syncthreads();

    const int NC = Dp / 8;  // 16
#pragma unroll 2
    for (int c = 0; c < NC; c++) {
        const int cur = c & 1;
        float4 pa, pb;
        const bool has = (c + 1 < NC);
        if (has) {
            pa = *(const float4*)(Xc + (size_t)nl * Dp + (c + 1) * 8 + kq * 4);
            pb = *(const float4*)(Yb + (size_t)nl * Dp + (c + 1) * 8 + kq * 4);
        }
#pragma unroll
        for (int kp = 0; kp < 4; kp++) {
            const ulonglong2* ap = (const ulonglong2*)&As2[cur][kp][ty * 8];
            ulonglong2 a01 = ap[0], a23 = ap[1], a45 = ap[2], a67 = ap[3];
            unsigned long long av[8] = {a01.x, a01.y, a23.x, a23.y,
                                        a45.x, a45.y, a67.x, a67.y};
            unsigned long long bv[4];
#pragma unroll
            for (int j = 0; j < 4; j++)
                bv[j] = *(const unsigned long long*)&Bt[cur][kp][j * 16 + tx];
#pragma unroll
            for (int i = 0; i < 8; i++)
#pragma unroll
                for (int j = 0; j < 4; j++)
                    acc[i][j] = fma2(av[i], bv[j], acc[i][j]);
        }
        if (has) {
            const int nx = cur ^ 1;
            As2[nx][2 * kq + 0][nl] = make_float2(pa.x, pa.y);
            As2[nx][2 * kq + 1][nl] = make_float2(pa.z, pa.w);
            Bt[nx][2 * kq + 0][nl] = make_float2(pb.x, pb.y);
            Bt[nx][2 * kq + 1][nl] = make_float2(pb.z, pb.w);
        }
        __syncthreads();
    }

    // epilogue: z = pair-sum; s (exact fp32), rounded P, sums of rounded P.
    // n = nt*64 + ty*8 + i;  m = mt*64 + j*16 + tx.
    float csum[4];
#pragma unroll
    for (int j = 0; j < 4; j++) csum[j] = 0.f;

#pragma unroll
    for (int i = 0; i < 8; i++) {
        const size_t off =
            ((size_t)(b * Np + nt * 64 + ty * 8 + i)) * Mp + mt * 64;
        float rs = 0.f;
#pragma unroll
        for (int j = 0; j < 4; j++) {
            float2 zz = up2(acc[i][j]);
            float z = zz.x + zz.y;
            float p = 1.f + __expf(z);
            float pr = tf32r(p);
            out_s[off + j * 16 + tx] = __logf(p) - 0.5f;
            g_P[off + j * 16 + tx] = pr;
            rs += pr;
            csum[j] += pr;
        }
        rs += __shfl_xor_sync(0xFFFFFFFFu, rs, 1);
        rs += __shfl_xor_sync(0xFFFFFFFFu, rs, 2);
        rs += __shfl_xor_sync(0xFFFFFFFFu, rs, 4);
        rs += __shfl_xor_sync(0xFFFFFFFFu, rs, 8);
        if (tx == 0) atomicAdd(&g_rs[b * Np + nt * 64 + ty * 8 + i], rs);
    }

#pragma unroll
    for (int j = 0; j < 4; j++) atomicAdd(&scs[j * 16 + tx], csum[j]);
    __syncthreads();
    if (tid < 64) atomicAdd(&g_cs[b * Mp + mt * 64 + tid], scs[tid]);
}

// ---------------------------------------------------------------------------
// K3 (wmma tf32, latency-restructured — R12 WIN, unchanged):
//  128 threads / CTA (4 warps), CTA tile 128 rows x 64 cols (d half),
//  4 CTAs/SM, 3-stage ring, k-chunk 16.
// ---------------------------------------------------------------------------
__global__ __launch_bounds__(128, 4) void k_attn(float* __restrict__ out_x,
                                                 float* __restrict__ out_y) {
    extern __shared__ __align__(16) float smf[];
    const uint32_t sb = s2u(smf);
    const int t = threadIdx.x;
    const int w = t >> 5;
    const int rt = blockIdx.x;          // 128-row tile
    const int d0 = blockIdx.y * 64;     // d half
    const int b = blockIdx.z & 31;
    const int mode = blockIdx.z >> 5;

    const float* Pb = g_P + (size_t)b * Np * Mp;
    const float* Bsrc = mode ? (g_Xr + (size_t)b * Np * Dp)
                             : (g_Yr + (size_t)b * Mp * Dp);

    const int m0 = w * 32;              // warp row base (warp tile 32x64)

    FragC acc[2][4];
#pragma unroll
    for (int i = 0; i < 2; i++)
#pragma unroll
        for (int j = 0; j < 4; j++) wmma::fill_fragment(acc[i][j], 0.f);

    // stage layout: A @ +0 (mode0: [128][20]; mode1: [16][132]); B @ +2560 ([16][68])
    auto load_chunk = [&](int c, int f) {
        uint32_t Ad = sb + (uint32_t)(f * STAGE_FL) * 4;
        uint32_t Bd = Ad + AB_OFF * 4;
        if (mode == 0) {
#pragma unroll
            for (int o = 0; o < 4; o++) {
                int idx = t + o * 128;
                int row = idx >> 2, q = idx & 3;
                cpa16(Ad + (uint32_t)((row * 20 + q * 4) * 4),
                      Pb + (size_t)(rt * 128 + row) * Mp + c * 16 + q * 4);
            }
        } else {
#pragma unroll
            for (int o = 0; o < 4; o++) {
                int idx = t + o * 128;
                int kr = idx >> 5, mq = idx & 31;
                cpa16(Ad + (uint32_t)((kr * 132 + mq * 4) * 4),
                      Pb + (size_t)(c * 16 + kr) * Mp + rt * 128 + mq * 4);
            }
        }
#pragma unroll
        for (int o = 0; o < 2; o++) {
            int idx = t + o * 128;
            int kr = idx >> 4, dq = idx & 15;
            cpa16(Bd + (uint32_t)((kr * 68 + dq * 4) * 4),
                  Bsrc + (size_t)(c * 16 + kr) * Dp + d0 + dq * 4);
        }
        CP_COMMIT();
    };

    load_chunk(0, 0);
    load_chunk(1, 1);
    const int NC = 64;   // K = 1024 in chunks of 16
    for (int c = 0; c < NC; c++) {
        if (c + 1 < NC) CP_WAIT1(); else CP_WAIT0();
        __syncthreads();
        if (c + 2 < NC) load_chunk(c + 2, (c + 2) % 3);
        const float* As_ = smf + (c % 3) * STAGE_FL;
        const float* Bs_ = As_ + AB_OFF;
        if (mode == 0) {
#pragma unroll
            for (int s = 0; s < 2; s++) {
                FragAR af[2];
                FragBR bf[4];
#pragma unroll
                for (int i = 0; i < 2; i++)
                    wmma::load_matrix_sync(af[i], As_ + (m0 + i * 16) * 20 + s * 8, 20);
#pragma unroll
                for (int j = 0; j < 4; j++)
                    wmma::load_matrix_sync(bf[j], Bs_ + (s * 8) * 68 + j * 16, 68);
#pragma unroll
                for (int i = 0; i < 2; i++)
#pragma unroll
                    for (int j = 0; j < 4; j++)
                        wmma::mma_sync(acc[i][j], af[i], bf[j], acc[i][j]);
            }
        } else {
#pragma unroll
            for (int s = 0; s < 2; s++) {
                FragAC af[2];
                FragBR bf[4];
#pragma unroll
                for (int i = 0; i < 2; i++)
                    wmma::load_matrix_sync(af[i], As_ + (s * 8) * 132 + m0 + i * 16, 132);
#pragma unroll
                for (int j = 0; j < 4; j++)
                    wmma::load_matrix_sync(bf[j], Bs_ + (s * 8) * 68 + j * 16, 68);
#pragma unroll
                for (int i = 0; i < 2; i++)
#pragma unroll
                    for (int j = 0; j < 4; j++)
                        wmma::mma_sync(acc[i][j], af[i], bf[j], acc[i][j]);
            }
        }
    }
    __syncthreads();

    // stash to smem [128][68], then normalized coalesced write-out
#pragma unroll
    for (int i = 0; i < 2; i++)
#pragma unroll
        for (int j = 0; j < 4; j++)
            wmma::store_matrix_sync(smf + (m0 + i * 16) * 68 + j * 16,
                                    acc[i][j], 68, wmma::mem_row_major);
    __syncthreads();

    {
        const int r = t;   // each thread owns one output row (64 cols)
        const float inv =
            1.f / (mode ? g_cs[b * Mp + rt * 128 + r]
                        : g_rs[b * Np + rt * 128 + r]);
        const float* rowp = smf + r * 68;
        float* outp = (mode ? out_y : out_x) +
                      (size_t)(b * 1024 + rt * 128 + r) * Dp + d0;
#pragma unroll
        for (int j = 0; j < 16; j++) {
            float4 v = *(const float4*)(rowp + j * 4);
            *(float4*)(outp + j * 4) =
                make_float4(v.x * inv, v.y * inv, v.z * inv, v.w * inv);
        }
    }
}

// ---------------------------------------------------------------------------
extern "C" void kernel_launch(void* const* d_in, const int* in_sizes, int n_in,
                              void* d_out, int out_size) {
    const float* Xs = (const float*)d_in[0];
    const float* Ys = (const float*)d_in[1];
    const float* W  = (const float*)d_in[2];
    const float* Aw = (const float*)d_in[3];
    const float* Ab = (const float*)d_in[4];

    float* out = (float*)d_out;
    float* out_x = out;                               // [B,N,D]
    float* out_y = out_x + (size_t)Bp * Np * Dp;      // [B,M,D]
    float* out_s = out_y + (size_t)Bp * Mp * Dp;      // [B,N,M]

    cudaFuncSetAttribute(k_attn, cudaFuncAttributeMaxDynamicSharedMemorySize,
                         SMEM_ATTN);

    k_zero<<<128, 256>>>();
    k_prep<<<4096, 256>>>(Xs, Ys);
    k_coeff<<<(Bp * Np) / 64, dim3(16, 16)>>>(W, Aw, Ab, Xs);
    k_scores<<<dim3(16, 16, 32), 128>>>(Ys, out_s);
    k_attn<<<dim3(8, 2, 64), 128, SMEM_ATTN>>>(out_x, out_y);
}